// round 15
// baseline (speedup 1.0000x reference)
#include <cuda_runtime.h>
#include <cuda_fp16.h>
#include <math.h>

#define BB 8
#define NN 1024
#define EE 768
#define HH 12
#define HD 64
#define GK 768

// fp16 scratch (device globals: allocation-free per harness rules)
__device__ __half g_query16[(size_t)BB*NN*EE];   // [8192,768]
__device__ __half g_qkvw16[(size_t)3*EE*EE];     // [2304,768]
__device__ __half g_outw16[(size_t)EE*EE];       // [768,768]
__device__ __half g_q16[(size_t)BB*HH*NN*HD];    // [B,H,N,64]  (pre-scaled 1/8)
__device__ __half g_k16[(size_t)BB*HH*NN*HD];    // [B,H,N,64]
__device__ __half g_vT16[(size_t)BB*HH*HD*NN];   // [B,H,64,N]  (transposed!)
__device__ __half g_ctx16[(size_t)BB*NN*EE];     // [8192,768]

__device__ __forceinline__ void mma16(float* c, const unsigned* a, const unsigned* b){
    asm volatile("mma.sync.aligned.m16n8k16.row.col.f32.f16.f16.f32 "
        "{%0,%1,%2,%3}, {%4,%5,%6,%7}, {%8,%9}, {%0,%1,%2,%3};\n"
        : "+f"(c[0]),"+f"(c[1]),"+f"(c[2]),"+f"(c[3])
        : "r"(a[0]),"r"(a[1]),"r"(a[2]),"r"(a[3]), "r"(b[0]),"r"(b[1]));
}
__device__ __forceinline__ void cpasync16(unsigned saddr, const void* gptr){
    asm volatile("cp.async.cg.shared.global [%0], [%1], 16;\n" :: "r"(saddr), "l"(gptr) : "memory");
}
__device__ __forceinline__ void cp_commit(){ asm volatile("cp.async.commit_group;\n" ::: "memory"); }
__device__ __forceinline__ void cp_wait0(){ asm volatile("cp.async.wait_group 0;\n" ::: "memory"); }
__device__ __forceinline__ void cp_wait1(){ asm volatile("cp.async.wait_group 1;\n" ::: "memory"); }
__device__ __forceinline__ void ldsm4(unsigned* r, unsigned saddr){
    asm volatile("ldmatrix.sync.aligned.m8n8.x4.shared.b16 {%0,%1,%2,%3}, [%4];\n"
        : "=r"(r[0]),"=r"(r[1]),"=r"(r[2]),"=r"(r[3]) : "r"(saddr));
}
__device__ __forceinline__ unsigned swz(unsigned x){ return x ^ ((x >> 3) & 0x70); }

// ---------------------------------------------------------------------------
// fp32 -> fp16 pre-convert (query, qkv_w, out_w)
// ---------------------------------------------------------------------------
__global__ void cvt_k(const float* __restrict__ q, const float* __restrict__ w1,
                      const float* __restrict__ w2)
{
    const int NQ = (BB*NN*EE)/4, NW1 = (3*EE*EE)/4, NW2 = (EE*EE)/4;
    const int stride = gridDim.x * blockDim.x;
    int i = blockIdx.x * blockDim.x + threadIdx.x;
    for (int j = i; j < NQ; j += stride) {
        float4 v = ((const float4*)q)[j];
        __half2 h0 = __floats2half2_rn(v.x, v.y), h1 = __floats2half2_rn(v.z, v.w);
        ((uint2*)g_query16)[j] = make_uint2(*(unsigned*)&h0, *(unsigned*)&h1);
    }
    for (int j = i; j < NW1; j += stride) {
        float4 v = ((const float4*)w1)[j];
        __half2 h0 = __floats2half2_rn(v.x, v.y), h1 = __floats2half2_rn(v.z, v.w);
        ((uint2*)g_qkvw16)[j] = make_uint2(*(unsigned*)&h0, *(unsigned*)&h1);
    }
    for (int j = i; j < NW2; j += stride) {
        float4 v = ((const float4*)w2)[j];
        __half2 h0 = __floats2half2_rn(v.x, v.y), h1 = __floats2half2_rn(v.z, v.w);
        ((uint2*)g_outw16)[j] = make_uint2(*(unsigned*)&h0, *(unsigned*)&h1);
    }
}

// ---------------------------------------------------------------------------
// fp16 NT GEMM: C[M,Ncols] = A[M,768] @ W[Ncols,768]^T + bias
// CTA 128x128, 128 thr (4 warps 2x2), warp 64x64, mma m16n8k16 f16->f32.
// k-chunks of 64 halves (128B swizzled rows), 3-stage cp.async ring,
// ONE __syncthreads per k-iter. 2 CTAs/SM.
// MODE 0: scatter to g_q16 (x0.125) / g_k16 / g_vT16 (transposed).
// MODE 1: fp32 out + bias.
// ---------------------------------------------------------------------------
#define TILE_B  (128*128)          // bytes per operand tile
#define STAGE_B (2*TILE_B)         // 32768 B
#define GSM     (3*STAGE_B)        // 98304 B
#define KT16    (GK/64)            // 12

template<int MODE>
__global__ void __launch_bounds__(128,2) gemm_k(
    const __half* __restrict__ Bw, const float* __restrict__ bias,
    float* __restrict__ Cout)
{
    extern __shared__ char smc[];
    const unsigned smb = (unsigned)__cvta_generic_to_shared(smc);
    const __half* A = (MODE == 0) ? g_query16 : g_ctx16;

    const int t = threadIdx.x;
    const int lane = t & 31, wid = t >> 5;
    const int group = lane >> 2, tig = lane & 3;
    const int wm = wid >> 1, wn = wid & 1;
    const int m0 = blockIdx.y * 128, n0 = blockIdx.x * 128;
    const int l16 = lane & 15, lh = lane >> 4;

    // loader: 1024 16B-segs per operand, 8 per thread (precomputed bases)
    const __half* aP[8]; const __half* bP[8]; unsigned so[8];
#pragma unroll
    for (int j = 0; j < 8; j++) {
        const int s = t + j * 128;
        const int row = s >> 3, c16 = s & 7;
        so[j] = swz((unsigned)(row * 128 + c16 * 16));
        aP[j] = A  + (size_t)(m0 + row) * GK + c16 * 8;
        bP[j] = Bw + (size_t)(n0 + row) * GK + c16 * 8;
    }
    auto load_stage = [&](int kt, int st){
        const unsigned ab = smb + (unsigned)st * STAGE_B;
        const unsigned bb = ab + TILE_B;
#pragma unroll
        for (int j = 0; j < 8; j++) {
            cpasync16(ab + so[j], aP[j] + kt * 64);
            cpasync16(bb + so[j], bP[j] + kt * 64);
        }
        cp_commit();
    };

    float acc[4][8][4];
#pragma unroll
    for (int mi = 0; mi < 4; mi++)
#pragma unroll
        for (int ni = 0; ni < 8; ni++)
#pragma unroll
            for (int v = 0; v < 4; v++) acc[mi][ni][v] = 0.f;

    load_stage(0, 0);
    load_stage(1, 1);

#pragma unroll 1
    for (int kt = 0; kt < KT16; kt++) {
        if (kt + 1 < KT16) cp_wait1(); else cp_wait0();
        __syncthreads();
        if (kt + 2 < KT16) load_stage(kt + 2, (kt + 2) % 3);

        const unsigned ab = smb + (unsigned)(kt % 3) * STAGE_B;
        const unsigned bb = ab + TILE_B;
#pragma unroll
        for (int ks = 0; ks < 4; ks++) {
            unsigned af[4][4], br[4][4];
#pragma unroll
            for (int mi = 0; mi < 4; mi++)
                ldsm4(af[mi], ab + swz((unsigned)((wm*64 + mi*16 + l16) * 128 + lh*16 + ks*32)));
#pragma unroll
            for (int p = 0; p < 4; p++)
                ldsm4(br[p], bb + swz((unsigned)((wn*64 + p*16 + l16) * 128 + lh*16 + ks*32)));
#pragma unroll
            for (int mi = 0; mi < 4; mi++)
#pragma unroll
                for (int p = 0; p < 4; p++) {
                    unsigned b0[2] = { br[p][0], br[p][2] };
                    unsigned b1[2] = { br[p][1], br[p][3] };
                    mma16(acc[mi][2*p],   af[mi], b0);
                    mma16(acc[mi][2*p+1], af[mi], b1);
                }
        }
    }

    // epilogue
    float bv0[8], bv1[8];
#pragma unroll
    for (int ni = 0; ni < 8; ni++) {
        const int c = n0 + wn * 64 + ni * 8 + 2 * tig;
        bv0[ni] = bias[c]; bv1[ni] = bias[c + 1];
    }

    if (MODE == 0) {
        const int which = blockIdx.x / 6;   // 0=q 1=k 2=v
        const float qs = (which == 0) ? 0.125f : 1.0f;
#pragma unroll
        for (int mi = 0; mi < 4; mi++)
#pragma unroll
            for (int rr = 0; rr < 2; rr++) {
                const int r  = m0 + wm * 64 + mi * 16 + group + rr * 8;
                const int bi = r >> 10, nidx = r & 1023;
#pragma unroll
                for (int ni = 0; ni < 8; ni++) {
                    const int c = n0 + wn * 64 + ni * 8 + 2 * tig;
                    const int e = c - which * 768;
                    const int h = e >> 6, d = e & 63;
                    const float vx = (acc[mi][ni][rr*2+0] + bv0[ni]) * qs;
                    const float vy = (acc[mi][ni][rr*2+1] + bv1[ni]) * qs;
                    if (which == 2) {
                        const size_t base = (((size_t)bi * HH + h) * HD + d) * NN + nidx;
                        g_vT16[base]      = __float2half_rn(vx);
                        g_vT16[base + NN] = __float2half_rn(vy);
                    } else {
                        __half* dst = (which == 0 ? g_q16 : g_k16)
                                    + ((((size_t)bi * HH + h) * NN + nidx) * HD + d);
                        *(__half2*)dst = __floats2half2_rn(vx, vy);
                    }
                }
            }
    } else {
#pragma unroll
        for (int mi = 0; mi < 4; mi++)
#pragma unroll
            for (int rr = 0; rr < 2; rr++) {
                const int r = m0 + wm * 64 + mi * 16 + group + rr * 8;
#pragma unroll
                for (int ni = 0; ni < 8; ni++) {
                    const int c = n0 + wn * 64 + ni * 8 + 2 * tig;
                    float2 val;
                    val.x = acc[mi][ni][rr*2+0] + bv0[ni];
                    val.y = acc[mi][ni][rr*2+1] + bv1[ni];
                    *(float2*)&Cout[(size_t)r * EE + c] = val;
                }
            }
    }
}

// ---------------------------------------------------------------------------
// Flash attention fp16: 128 thr (4 warps x 32 q-rows), q-tile 128, kv-tile 64.
// Qs[128][64h] (pre-scaled), Ks/VTs double-buffered cp.async, Ps[128][64h].
// ONE __syncthreads per kv-iter (load of next tile issued after it).
// ---------------------------------------------------------------------------
#define ATT_Q   0
#define ATT_K0  16384
#define ATT_V0  32768
#define ATT_P   49152
#define ATT_SM  65536

__global__ void __launch_bounds__(128,2) attn_k()
{
    extern __shared__ char smc[];
    const unsigned smb = (unsigned)__cvta_generic_to_shared(smc);

    const int t = threadIdx.x, lane = t & 31, wid = t >> 5;
    const int group = lane >> 2, tig = lane & 3;
    const int l16 = lane & 15, lh = lane >> 4;
    const int bh = blockIdx.y, qt = blockIdx.x;

    // K/V loader: 512 16B-segs per operand, 4 per thread
    const __half* kP[4]; const __half* vP[4]; unsigned kso[4];
#pragma unroll
    for (int j = 0; j < 4; j++) {
        const int s = t + j * 128;
        const int row = s >> 3, c16 = s & 7;
        kso[j] = swz((unsigned)(row * 128 + c16 * 16));
        kP[j] = g_k16  + ((size_t)bh * NN + row) * HD + c16 * 8;
        vP[j] = g_vT16 + ((size_t)bh * HD + row) * NN + c16 * 8;
    }
    auto load_kv = [&](int kt, int st){
        const unsigned kb = smb + ATT_K0 + (unsigned)st * 8192u;
        const unsigned vb = smb + ATT_V0 + (unsigned)st * 8192u;
#pragma unroll
        for (int j = 0; j < 4; j++) {
            cpasync16(kb + kso[j], kP[j] + (size_t)(kt * 64) * HD);  // +64 rows
            cpasync16(vb + kso[j], vP[j] + kt * 64);                 // +64 cols
        }
        cp_commit();
    };

    {   // stage Q (1024 segs, 8/thread) + K/V tile 0 in ONE group
        const __half* gq = g_q16 + ((size_t)bh * NN + qt * 128) * HD;
#pragma unroll
        for (int j = 0; j < 8; j++) {
            const int s = t + j * 128;
            const int row = s >> 3, c16 = s & 7;
            cpasync16(smb + ATT_Q + swz((unsigned)(row * 128 + c16 * 16)),
                      gq + (size_t)row * HD + c16 * 8);
        }
        load_kv(0, 0);   // commits the combined group
    }

    float oc[2][8][4];
#pragma unroll
    for (int mi = 0; mi < 2; mi++)
#pragma unroll
        for (int ni = 0; ni < 8; ni++)
#pragma unroll
            for (int v = 0; v < 4; v++) oc[mi][ni][v] = 0.f;
    float mprev[2][2] = {{-1e30f,-1e30f},{-1e30f,-1e30f}};
    float lsum[2][2]  = {{0.f,0.f},{0.f,0.f}};

#pragma unroll 1
    for (int kt = 0; kt < 16; kt++) {
        cp_wait0();
        __syncthreads();            // all copies visible; all warps done with prev bufs
        if (kt + 1 < 16) load_kv(kt + 1, (kt + 1) & 1);

        const unsigned kb = smb + ATT_K0 + (unsigned)(kt & 1) * 8192u;
        const unsigned vb = smb + ATT_V0 + (unsigned)(kt & 1) * 8192u;

        // S = Q K^T : per warp 32 q-rows x 64 keys (k = d, 4 steps of 16)
        float sc[2][8][4];
#pragma unroll
        for (int mi = 0; mi < 2; mi++)
#pragma unroll
            for (int ni = 0; ni < 8; ni++)
#pragma unroll
                for (int v = 0; v < 4; v++) sc[mi][ni][v] = 0.f;
#pragma unroll
        for (int ks = 0; ks < 4; ks++) {
            unsigned a[2][4];
#pragma unroll
            for (int mi = 0; mi < 2; mi++)
                ldsm4(a[mi], smb + ATT_Q + swz((unsigned)((wid*32 + mi*16 + l16) * 128 + lh*16 + ks*32)));
#pragma unroll
            for (int p = 0; p < 4; p++) {
                unsigned br[4];
                ldsm4(br, kb + swz((unsigned)((p*16 + l16) * 128 + lh*16 + ks*32)));
                unsigned b0[2] = { br[0], br[2] };
                unsigned b1[2] = { br[1], br[3] };
#pragma unroll
                for (int mi = 0; mi < 2; mi++) {
                    mma16(sc[mi][2*p],   a[mi], b0);
                    mma16(sc[mi][2*p+1], a[mi], b1);
                }
            }
        }

        // online softmax (4 row-stats per thread; stats across lane quad)
#pragma unroll
        for (int mi = 0; mi < 2; mi++)
#pragma unroll
            for (int rr = 0; rr < 2; rr++) {
                float tm = -1e30f;
#pragma unroll
                for (int ni = 0; ni < 8; ni++)
                    tm = fmaxf(tm, fmaxf(sc[mi][ni][rr*2], sc[mi][ni][rr*2+1]));
                tm = fmaxf(tm, __shfl_xor_sync(0xffffffffu, tm, 1));
                tm = fmaxf(tm, __shfl_xor_sync(0xffffffffu, tm, 2));
                const float mnew = fmaxf(mprev[mi][rr], tm);
                const float corr = __expf(mprev[mi][rr] - mnew);
                mprev[mi][rr] = mnew;
                float rs = 0.f;
#pragma unroll
                for (int ni = 0; ni < 8; ni++) {
                    const float p0 = __expf(sc[mi][ni][rr*2]   - mnew);
                    const float p1 = __expf(sc[mi][ni][rr*2+1] - mnew);
                    sc[mi][ni][rr*2] = p0; sc[mi][ni][rr*2+1] = p1;
                    rs += p0 + p1;
                }
                rs += __shfl_xor_sync(0xffffffffu, rs, 1);
                rs += __shfl_xor_sync(0xffffffffu, rs, 2);
                lsum[mi][rr] = lsum[mi][rr] * corr + rs;
#pragma unroll
                for (int ni = 0; ni < 8; ni++) {
                    oc[mi][ni][rr*2]   *= corr;
                    oc[mi][ni][rr*2+1] *= corr;
                }
            }

        // stage P as half2 [m][key] (own warp's 32 rows only)
#pragma unroll
        for (int mi = 0; mi < 2; mi++) {
            const int row0 = wid * 32 + mi * 16 + group;
#pragma unroll
            for (int ni = 0; ni < 8; ni++) {
                const int col = ni * 8 + 2 * tig;
                __half2 v0 = __floats2half2_rn(sc[mi][ni][0], sc[mi][ni][1]);
                __half2 v1 = __floats2half2_rn(sc[mi][ni][2], sc[mi][ni][3]);
                *(__half2*)(smc + ATT_P + swz((unsigned)( row0      * 128 + col * 2))) = v0;
                *(__half2*)(smc + ATT_P + swz((unsigned)((row0 + 8) * 128 + col * 2))) = v1;
            }
        }
        __syncwarp();

        // O += P V  (A = P rows, B = V^T rows d; k = keys, 4 steps of 16)
#pragma unroll
        for (int ks = 0; ks < 4; ks++) {
            unsigned a[2][4];
#pragma unroll
            for (int mi = 0; mi < 2; mi++)
                ldsm4(a[mi], smb + ATT_P + swz((unsigned)((wid*32 + mi*16 + l16) * 128 + lh*16 + ks*32)));
#pragma unroll
            for (int p = 0; p < 4; p++) {
                unsigned br[4];
                ldsm4(br, vb + swz((unsigned)((p*16 + l16) * 128 + lh*16 + ks*32)));
                unsigned b0[2] = { br[0], br[2] };
                unsigned b1[2] = { br[1], br[3] };
#pragma unroll
                for (int mi = 0; mi < 2; mi++) {
                    mma16(oc[mi][2*p],   a[mi], b0);
                    mma16(oc[mi][2*p+1], a[mi], b1);
                }
            }
        }
    }

    // normalize + write ctx16 [8192,768] at col h*64
    const int bi = bh / HH, h = bh % HH;
#pragma unroll
    for (int mi = 0; mi < 2; mi++)
#pragma unroll
        for (int rr = 0; rr < 2; rr++) {
            const float inv = 1.0f / lsum[mi][rr];
            const int qrow = qt * 128 + wid * 32 + mi * 16 + group + rr * 8;
            const size_t rowoff = ((size_t)bi * NN + qrow) * EE + h * HD;
#pragma unroll
            for (int ni = 0; ni < 8; ni++) {
                __half2 v = __floats2half2_rn(oc[mi][ni][rr*2] * inv, oc[mi][ni][rr*2+1] * inv);
                *(__half2*)&g_ctx16[rowoff + ni * 8 + 2 * tig] = v;
            }
        }
}

// ---------------------------------------------------------------------------
extern "C" void kernel_launch(void* const* d_in, const int* in_sizes, int n_in,
                              void* d_out, int out_size)
{
    const float* query = (const float*)d_in[0];
    const float* qkv_w = (const float*)d_in[1];
    const float* qkv_b = (const float*)d_in[2];
    const float* out_w = (const float*)d_in[3];
    const float* out_b = (const float*)d_in[4];
    float* out = (float*)d_out;

    cudaFuncSetAttribute(gemm_k<0>, cudaFuncAttributeMaxDynamicSharedMemorySize, GSM);
    cudaFuncSetAttribute(gemm_k<1>, cudaFuncAttributeMaxDynamicSharedMemorySize, GSM);
    cudaFuncSetAttribute(attn_k,    cudaFuncAttributeMaxDynamicSharedMemorySize, ATT_SM);

    static __half *w1p = nullptr, *w2p = nullptr;
    if (!w1p) { cudaGetSymbolAddress((void**)&w1p, g_qkvw16);
                cudaGetSymbolAddress((void**)&w2p, g_outw16); }

    cvt_k<<<1024, 256>>>(query, qkv_w, out_w);
    gemm_k<0><<<dim3(18, 64), 128, GSM>>>(w1p, qkv_b, nullptr);
    attn_k<<<dim3(8, 96), 128, ATT_SM>>>();
    gemm_k<1><<<dim3(6, 64), 128, GSM>>>(w2p, out_b, out);
}

// round 16
// speedup vs baseline: 1.0049x; 1.0049x over previous
#include <cuda_runtime.h>
#include <cuda_fp16.h>
#include <math.h>

#define BB 8
#define NN 1024
#define EE 768
#define HH 12
#define HD 64
#define GK 768

// fp16 scratch (device globals: allocation-free per harness rules)
__device__ __half g_query16[(size_t)BB*NN*EE];   // [8192,768]
__device__ __half g_qkvw16[(size_t)3*EE*EE];     // [2304,768]
__device__ __half g_outw16[(size_t)EE*EE];       // [768,768]
__device__ __half g_q16[(size_t)BB*HH*NN*HD];    // [B,H,N,64]  (pre-scaled 1/8)
__device__ __half g_k16[(size_t)BB*HH*NN*HD];    // [B,H,N,64]
__device__ __half g_vT16[(size_t)BB*HH*HD*NN];   // [B,H,64,N]  (transposed!)
__device__ __half g_ctx16[(size_t)BB*NN*EE];     // [8192,768]

__device__ __forceinline__ void mma16(float* c, const unsigned* a, const unsigned* b){
    asm volatile("mma.sync.aligned.m16n8k16.row.col.f32.f16.f16.f32 "
        "{%0,%1,%2,%3}, {%4,%5,%6,%7}, {%8,%9}, {%0,%1,%2,%3};\n"
        : "+f"(c[0]),"+f"(c[1]),"+f"(c[2]),"+f"(c[3])
        : "r"(a[0]),"r"(a[1]),"r"(a[2]),"r"(a[3]), "r"(b[0]),"r"(b[1]));
}
__device__ __forceinline__ void cpasync16(unsigned saddr, const void* gptr){
    asm volatile("cp.async.cg.shared.global [%0], [%1], 16;\n" :: "r"(saddr), "l"(gptr) : "memory");
}
__device__ __forceinline__ void cp_commit(){ asm volatile("cp.async.commit_group;\n" ::: "memory"); }
__device__ __forceinline__ void cp_wait0(){ asm volatile("cp.async.wait_group 0;\n" ::: "memory"); }
__device__ __forceinline__ void cp_wait1(){ asm volatile("cp.async.wait_group 1;\n" ::: "memory"); }
__device__ __forceinline__ void ldsm4(unsigned* r, unsigned saddr){
    asm volatile("ldmatrix.sync.aligned.m8n8.x4.shared.b16 {%0,%1,%2,%3}, [%4];\n"
        : "=r"(r[0]),"=r"(r[1]),"=r"(r[2]),"=r"(r[3]) : "r"(saddr));
}
__device__ __forceinline__ unsigned swz(unsigned x){ return x ^ ((x >> 3) & 0x70); }

// ---------------------------------------------------------------------------
// fp32 -> fp16 pre-convert (query, qkv_w, out_w)
// ---------------------------------------------------------------------------
__global__ void cvt_k(const float* __restrict__ q, const float* __restrict__ w1,
                      const float* __restrict__ w2)
{
    const int NQ = (BB*NN*EE)/4, NW1 = (3*EE*EE)/4, NW2 = (EE*EE)/4;
    const int stride = gridDim.x * blockDim.x;
    int i = blockIdx.x * blockDim.x + threadIdx.x;
    for (int j = i; j < NQ; j += stride) {
        float4 v = ((const float4*)q)[j];
        __half2 h0 = __floats2half2_rn(v.x, v.y), h1 = __floats2half2_rn(v.z, v.w);
        ((uint2*)g_query16)[j] = make_uint2(*(unsigned*)&h0, *(unsigned*)&h1);
    }
    for (int j = i; j < NW1; j += stride) {
        float4 v = ((const float4*)w1)[j];
        __half2 h0 = __floats2half2_rn(v.x, v.y), h1 = __floats2half2_rn(v.z, v.w);
        ((uint2*)g_qkvw16)[j] = make_uint2(*(unsigned*)&h0, *(unsigned*)&h1);
    }
    for (int j = i; j < NW2; j += stride) {
        float4 v = ((const float4*)w2)[j];
        __half2 h0 = __floats2half2_rn(v.x, v.y), h1 = __floats2half2_rn(v.z, v.w);
        ((uint2*)g_outw16)[j] = make_uint2(*(unsigned*)&h0, *(unsigned*)&h1);
    }
}

// ---------------------------------------------------------------------------
// fp16 NT GEMM: C[M,Ncols] = A[M,768] @ W[Ncols,768]^T + bias
// CTA 128x128, 128 thr (4 warps 2x2), warp 64x64, mma m16n8k16 f16->f32.
// k-chunks of 64 halves (128B swizzled rows), 3-stage cp.async ring,
// ONE __syncthreads per k-iter. 2 CTAs/SM.
// MODE 0: scatter to g_q16 (x0.125) / g_k16 / g_vT16 (transposed).
// MODE 1: fp32 out + bias.
// ---------------------------------------------------------------------------
#define TILE_B  (128*128)          // bytes per operand tile
#define STAGE_B (2*TILE_B)         // 32768 B
#define GSM     (3*STAGE_B)        // 98304 B
#define KT16    (GK/64)            // 12

template<int MODE>
__global__ void __launch_bounds__(128,2) gemm_k(
    const __half* __restrict__ Bw, const float* __restrict__ bias,
    float* __restrict__ Cout)
{
    extern __shared__ char smc[];
    const unsigned smb = (unsigned)__cvta_generic_to_shared(smc);
    const __half* A = (MODE == 0) ? g_query16 : g_ctx16;

    const int t = threadIdx.x;
    const int lane = t & 31, wid = t >> 5;
    const int group = lane >> 2, tig = lane & 3;
    const int wm = wid >> 1, wn = wid & 1;
    const int m0 = blockIdx.y * 128, n0 = blockIdx.x * 128;
    const int l16 = lane & 15, lh = lane >> 4;

    // loader: 1024 16B-segs per operand, 8 per thread (precomputed bases)
    const __half* aP[8]; const __half* bP[8]; unsigned so[8];
#pragma unroll
    for (int j = 0; j < 8; j++) {
        const int s = t + j * 128;
        const int row = s >> 3, c16 = s & 7;
        so[j] = swz((unsigned)(row * 128 + c16 * 16));
        aP[j] = A  + (size_t)(m0 + row) * GK + c16 * 8;
        bP[j] = Bw + (size_t)(n0 + row) * GK + c16 * 8;
    }
    auto load_stage = [&](int kt, int st){
        const unsigned ab = smb + (unsigned)st * STAGE_B;
        const unsigned bb = ab + TILE_B;
#pragma unroll
        for (int j = 0; j < 8; j++) {
            cpasync16(ab + so[j], aP[j] + kt * 64);
            cpasync16(bb + so[j], bP[j] + kt * 64);
        }
        cp_commit();
    };

    float acc[4][8][4];
#pragma unroll
    for (int mi = 0; mi < 4; mi++)
#pragma unroll
        for (int ni = 0; ni < 8; ni++)
#pragma unroll
            for (int v = 0; v < 4; v++) acc[mi][ni][v] = 0.f;

    load_stage(0, 0);
    load_stage(1, 1);

#pragma unroll 1
    for (int kt = 0; kt < KT16; kt++) {
        if (kt + 1 < KT16) cp_wait1(); else cp_wait0();
        __syncthreads();
        if (kt + 2 < KT16) load_stage(kt + 2, (kt + 2) % 3);

        const unsigned ab = smb + (unsigned)(kt % 3) * STAGE_B;
        const unsigned bb = ab + TILE_B;
#pragma unroll
        for (int ks = 0; ks < 4; ks++) {
            unsigned af[4][4], br[4][4];
#pragma unroll
            for (int mi = 0; mi < 4; mi++)
                ldsm4(af[mi], ab + swz((unsigned)((wm*64 + mi*16 + l16) * 128 + lh*16 + ks*32)));
#pragma unroll
            for (int p = 0; p < 4; p++)
                ldsm4(br[p], bb + swz((unsigned)((wn*64 + p*16 + l16) * 128 + lh*16 + ks*32)));
#pragma unroll
            for (int mi = 0; mi < 4; mi++)
#pragma unroll
                for (int p = 0; p < 4; p++) {
                    unsigned b0[2] = { br[p][0], br[p][2] };
                    unsigned b1[2] = { br[p][1], br[p][3] };
                    mma16(acc[mi][2*p],   af[mi], b0);
                    mma16(acc[mi][2*p+1], af[mi], b1);
                }
        }
    }

    // epilogue
    float bv0[8], bv1[8];
#pragma unroll
    for (int ni = 0; ni < 8; ni++) {
        const int c = n0 + wn * 64 + ni * 8 + 2 * tig;
        bv0[ni] = bias[c]; bv1[ni] = bias[c + 1];
    }

    if (MODE == 0) {
        const int which = blockIdx.x / 6;   // 0=q 1=k 2=v
        const float qs = (which == 0) ? 0.125f : 1.0f;
#pragma unroll
        for (int mi = 0; mi < 4; mi++)
#pragma unroll
            for (int rr = 0; rr < 2; rr++) {
                const int r  = m0 + wm * 64 + mi * 16 + group + rr * 8;
                const int bi = r >> 10, nidx = r & 1023;
#pragma unroll
                for (int ni = 0; ni < 8; ni++) {
                    const int c = n0 + wn * 64 + ni * 8 + 2 * tig;
                    const int e = c - which * 768;
                    const int h = e >> 6, d = e & 63;
                    const float vx = (acc[mi][ni][rr*2+0] + bv0[ni]) * qs;
                    const float vy = (acc[mi][ni][rr*2+1] + bv1[ni]) * qs;
                    if (which == 2) {
                        const size_t base = (((size_t)bi * HH + h) * HD + d) * NN + nidx;
                        g_vT16[base]      = __float2half_rn(vx);
                        g_vT16[base + NN] = __float2half_rn(vy);
                    } else {
                        __half* dst = (which == 0 ? g_q16 : g_k16)
                                    + ((((size_t)bi * HH + h) * NN + nidx) * HD + d);
                        *(__half2*)dst = __floats2half2_rn(vx, vy);
                    }
                }
            }
    } else {
#pragma unroll
        for (int mi = 0; mi < 4; mi++)
#pragma unroll
            for (int rr = 0; rr < 2; rr++) {
                const int r = m0 + wm * 64 + mi * 16 + group + rr * 8;
#pragma unroll
                for (int ni = 0; ni < 8; ni++) {
                    const int c = n0 + wn * 64 + ni * 8 + 2 * tig;
                    float2 val;
                    val.x = acc[mi][ni][rr*2+0] + bv0[ni];
                    val.y = acc[mi][ni][rr*2+1] + bv1[ni];
                    *(float2*)&Cout[(size_t)r * EE + c] = val;
                }
            }
    }
}

// ---------------------------------------------------------------------------
// Flash attention fp16: 128 thr (4 warps x 32 q-rows), q-tile 128, kv-tile 64.
// Qs[128][64h] (pre-scaled), Ks/VTs double-buffered cp.async, Ps[128][64h].
// ONE __syncthreads per kv-iter (load of next tile issued after it).
// ---------------------------------------------------------------------------
#define ATT_Q   0
#define ATT_K0  16384
#define ATT_V0  32768
#define ATT_P   49152
#define ATT_SM  65536

__global__ void __launch_bounds__(128,2) attn_k()
{
    extern __shared__ char smc[];
    const unsigned smb = (unsigned)__cvta_generic_to_shared(smc);

    const int t = threadIdx.x, lane = t & 31, wid = t >> 5;
    const int group = lane >> 2, tig = lane & 3;
    const int l16 = lane & 15, lh = lane >> 4;
    const int bh = blockIdx.y, qt = blockIdx.x;

    // K/V loader: 512 16B-segs per operand, 4 per thread
    const __half* kP[4]; const __half* vP[4]; unsigned kso[4];
#pragma unroll
    for (int j = 0; j < 4; j++) {
        const int s = t + j * 128;
        const int row = s >> 3, c16 = s & 7;
        kso[j] = swz((unsigned)(row * 128 + c16 * 16));
        kP[j] = g_k16  + ((size_t)bh * NN + row) * HD + c16 * 8;
        vP[j] = g_vT16 + ((size_t)bh * HD + row) * NN + c16 * 8;
    }
    auto load_kv = [&](int kt, int st){
        const unsigned kb = smb + ATT_K0 + (unsigned)st * 8192u;
        const unsigned vb = smb + ATT_V0 + (unsigned)st * 8192u;
#pragma unroll
        for (int j = 0; j < 4; j++) {
            cpasync16(kb + kso[j], kP[j] + (size_t)(kt * 64) * HD);  // +64 rows
            cpasync16(vb + kso[j], vP[j] + kt * 64);                 // +64 cols
        }
        cp_commit();
    };

    {   // stage Q (1024 segs, 8/thread) + K/V tile 0 in ONE group
        const __half* gq = g_q16 + ((size_t)bh * NN + qt * 128) * HD;
#pragma unroll
        for (int j = 0; j < 8; j++) {
            const int s = t + j * 128;
            const int row = s >> 3, c16 = s & 7;
            cpasync16(smb + ATT_Q + swz((unsigned)(row * 128 + c16 * 16)),
                      gq + (size_t)row * HD + c16 * 8);
        }
        load_kv(0, 0);   // commits the combined group
    }

    float oc[2][8][4];
#pragma unroll
    for (int mi = 0; mi < 2; mi++)
#pragma unroll
        for (int ni = 0; ni < 8; ni++)
#pragma unroll
            for (int v = 0; v < 4; v++) oc[mi][ni][v] = 0.f;
    float mprev[2][2] = {{-1e30f,-1e30f},{-1e30f,-1e30f}};
    float lsum[2][2]  = {{0.f,0.f},{0.f,0.f}};

#pragma unroll 1
    for (int kt = 0; kt < 16; kt++) {
        cp_wait0();
        __syncthreads();            // all copies visible; all warps done with prev bufs
        if (kt + 1 < 16) load_kv(kt + 1, (kt + 1) & 1);

        const unsigned kb = smb + ATT_K0 + (unsigned)(kt & 1) * 8192u;
        const unsigned vb = smb + ATT_V0 + (unsigned)(kt & 1) * 8192u;

        // S = Q K^T : per warp 32 q-rows x 64 keys (k = d, 4 steps of 16)
        float sc[2][8][4];
#pragma unroll
        for (int mi = 0; mi < 2; mi++)
#pragma unroll
            for (int ni = 0; ni < 8; ni++)
#pragma unroll
                for (int v = 0; v < 4; v++) sc[mi][ni][v] = 0.f;
#pragma unroll
        for (int ks = 0; ks < 4; ks++) {
            unsigned a[2][4];
#pragma unroll
            for (int mi = 0; mi < 2; mi++)
                ldsm4(a[mi], smb + ATT_Q + swz((unsigned)((wid*32 + mi*16 + l16) * 128 + lh*16 + ks*32)));
#pragma unroll
            for (int p = 0; p < 4; p++) {
                unsigned br[4];
                ldsm4(br, kb + swz((unsigned)((p*16 + l16) * 128 + lh*16 + ks*32)));
                unsigned b0[2] = { br[0], br[2] };
                unsigned b1[2] = { br[1], br[3] };
#pragma unroll
                for (int mi = 0; mi < 2; mi++) {
                    mma16(sc[mi][2*p],   a[mi], b0);
                    mma16(sc[mi][2*p+1], a[mi], b1);
                }
            }
        }

        // online softmax (4 row-stats per thread; stats across lane quad)
#pragma unroll
        for (int mi = 0; mi < 2; mi++)
#pragma unroll
            for (int rr = 0; rr < 2; rr++) {
                float tm = -1e30f;
#pragma unroll
                for (int ni = 0; ni < 8; ni++)
                    tm = fmaxf(tm, fmaxf(sc[mi][ni][rr*2], sc[mi][ni][rr*2+1]));
                tm = fmaxf(tm, __shfl_xor_sync(0xffffffffu, tm, 1));
                tm = fmaxf(tm, __shfl_xor_sync(0xffffffffu, tm, 2));
                const float mnew = fmaxf(mprev[mi][rr], tm);
                const float corr = __expf(mprev[mi][rr] - mnew);
                mprev[mi][rr] = mnew;
                float rs = 0.f;
#pragma unroll
                for (int ni = 0; ni < 8; ni++) {
                    const float p0 = __expf(sc[mi][ni][rr*2]   - mnew);
                    const float p1 = __expf(sc[mi][ni][rr*2+1] - mnew);
                    sc[mi][ni][rr*2] = p0; sc[mi][ni][rr*2+1] = p1;
                    rs += p0 + p1;
                }
                rs += __shfl_xor_sync(0xffffffffu, rs, 1);
                rs += __shfl_xor_sync(0xffffffffu, rs, 2);
                lsum[mi][rr] = lsum[mi][rr] * corr + rs;
#pragma unroll
                for (int ni = 0; ni < 8; ni++) {
                    oc[mi][ni][rr*2]   *= corr;
                    oc[mi][ni][rr*2+1] *= corr;
                }
            }

        // stage P as half2 [m][key] (own warp's 32 rows only)
#pragma unroll
        for (int mi = 0; mi < 2; mi++) {
            const int row0 = wid * 32 + mi * 16 + group;
#pragma unroll
            for (int ni = 0; ni < 8; ni++) {
                const int col = ni * 8 + 2 * tig;
                __half2 v0 = __floats2half2_rn(sc[mi][ni][0], sc[mi][ni][1]);
                __half2 v1 = __floats2half2_rn(sc[mi][ni][2], sc[mi][ni][3]);
                *(__half2*)(smc + ATT_P + swz((unsigned)( row0      * 128 + col * 2))) = v0;
                *(__half2*)(smc + ATT_P + swz((unsigned)((row0 + 8) * 128 + col * 2))) = v1;
            }
        }
        __syncwarp();

        // O += P V  (A = P rows, B = V^T rows d; k = keys, 4 steps of 16)
#pragma unroll
        for (int ks = 0; ks < 4; ks++) {
            unsigned a[2][4];
#pragma unroll
            for (int mi = 0; mi < 2; mi++)
                ldsm4(a[mi], smb + ATT_P + swz((unsigned)((wid*32 + mi*16 + l16) * 128 + lh*16 + ks*32)));
#pragma unroll
            for (int p = 0; p < 4; p++) {
                unsigned br[4];
                ldsm4(br, vb + swz((unsigned)((p*16 + l16) * 128 + lh*16 + ks*32)));
                unsigned b0[2] = { br[0], br[2] };
                unsigned b1[2] = { br[1], br[3] };
#pragma unroll
                for (int mi = 0; mi < 2; mi++) {
                    mma16(oc[mi][2*p],   a[mi], b0);
                    mma16(oc[mi][2*p+1], a[mi], b1);
                }
            }
        }
    }

    // normalize + write ctx16 [8192,768] at col h*64
    const int bi = bh / HH, h = bh % HH;
#pragma unroll
    for (int mi = 0; mi < 2; mi++)
#pragma unroll
        for (int rr = 0; rr < 2; rr++) {
            const float inv = 1.0f / lsum[mi][rr];
            const int qrow = qt * 128 + wid * 32 + mi * 16 + group + rr * 8;
            const size_t rowoff = ((size_t)bi * NN + qrow) * EE + h * HD;
#pragma unroll
            for (int ni = 0; ni < 8; ni++) {
                __half2 v = __floats2half2_rn(oc[mi][ni][rr*2] * inv, oc[mi][ni][rr*2+1] * inv);
                *(__half2*)&g_ctx16[rowoff + ni * 8 + 2 * tig] = v;
            }
        }
}

// ---------------------------------------------------------------------------
extern "C" void kernel_launch(void* const* d_in, const int* in_sizes, int n_in,
                              void* d_out, int out_size)
{
    const float* query = (const float*)d_in[0];
    const float* qkv_w = (const float*)d_in[1];
    const float* qkv_b = (const float*)d_in[2];
    const float* out_w = (const float*)d_in[3];
    const float* out_b = (const float*)d_in[4];
    float* out = (float*)d_out;

    cudaFuncSetAttribute(gemm_k<0>, cudaFuncAttributeMaxDynamicSharedMemorySize, GSM);
    cudaFuncSetAttribute(gemm_k<1>, cudaFuncAttributeMaxDynamicSharedMemorySize, GSM);
    cudaFuncSetAttribute(attn_k,    cudaFuncAttributeMaxDynamicSharedMemorySize, ATT_SM);

    static __half *w1p = nullptr, *w2p = nullptr;
    if (!w1p) { cudaGetSymbolAddress((void**)&w1p, g_qkvw16);
                cudaGetSymbolAddress((void**)&w2p, g_outw16); }

    cvt_k<<<1024, 256>>>(query, qkv_w, out_w);
    gemm_k<0><<<dim3(18, 64), 128, GSM>>>(w1p, qkv_b, nullptr);
    attn_k<<<dim3(8, 96), 128, ATT_SM>>>();
    gemm_k<1><<<dim3(6, 64), 128, GSM>>>(w2p, out_b, out);
}